// round 4
// baseline (speedup 1.0000x reference)
#include <cuda_runtime.h>
#include <cuda_bf16.h>
#include <cstdint>

#define NB   32
#define HW   48
#define DIM  384
#define D3   1152
#define NHE  8
#define HDI  48
#define WSZ  6
#define VTOK 36
#define NM   2048
#define TOK  73728
#define KDIM 384
#define SCALE 0.14433756729740643f

// ---------------- scratch (device globals) ----------------------------------
__device__ __nv_bfloat16 g_x_hi[(size_t)TOK * KDIM];
__device__ __nv_bfloat16 g_x_lo[(size_t)TOK * KDIM];
__device__ __nv_bfloat16 g_wq_hi[(size_t)D3 * KDIM];   // transposed [n][k]
__device__ __nv_bfloat16 g_wq_lo[(size_t)D3 * KDIM];
__device__ __nv_bfloat16 g_wp_hi[(size_t)DIM * KDIM];  // transposed [n][k]
__device__ __nv_bfloat16 g_wp_lo[(size_t)DIM * KDIM];
__device__ float         g_qkv[(size_t)TOK * D3];      // raster pixel order
__device__ __nv_bfloat16 g_att_hi[(size_t)TOK * DIM];  // raster pixel order
__device__ __nv_bfloat16 g_att_lo[(size_t)TOK * DIM];

__device__ __forceinline__ void split2(float v, uint16_t& h, uint16_t& l) {
    __nv_bfloat16 hb = __float2bfloat16_rn(v);
    float r = v - __bfloat162float(hb);
    __nv_bfloat16 lb = __float2bfloat16_rn(r);
    h = __bfloat16_as_ushort(hb);
    l = __bfloat16_as_ushort(lb);
}

// ---------------- prep kernels ----------------------------------------------
__global__ __launch_bounds__(256) void split_x(const float* __restrict__ x) {
    size_t i = (size_t)blockIdx.x * 256 + threadIdx.x;
    float4 v = ((const float4*)x)[i];
    uint16_t h0, h1, h2, h3, l0, l1, l2, l3;
    split2(v.x, h0, l0); split2(v.y, h1, l1);
    split2(v.z, h2, l2); split2(v.w, h3, l3);
    uint2 H, L;
    H.x = (uint32_t)h0 | ((uint32_t)h1 << 16);
    H.y = (uint32_t)h2 | ((uint32_t)h3 << 16);
    L.x = (uint32_t)l0 | ((uint32_t)l1 << 16);
    L.y = (uint32_t)l2 | ((uint32_t)l3 << 16);
    ((uint2*)g_x_hi)[i] = H;
    ((uint2*)g_x_lo)[i] = L;
}

template <int NT>
__global__ __launch_bounds__(256) void split_w(const float* __restrict__ w) {
    int idx = blockIdx.x * 256 + threadIdx.x;       // idx = k*NT + n
    int k = idx / NT, n = idx - k * NT;
    uint16_t h, l;
    split2(w[idx], h, l);
    __nv_bfloat16* wh = (NT == D3) ? g_wq_hi : g_wp_hi;
    __nv_bfloat16* wl = (NT == D3) ? g_wq_lo : g_wp_lo;
    ((uint16_t*)wh)[(size_t)n * KDIM + k] = h;
    ((uint16_t*)wl)[(size_t)n * KDIM + k] = l;
}

// ---------------- bf16-split tensor-core GEMM -------------------------------
// Smem layout: per stage, A tile 128 rows x 128B (32 hi bf16 | 32 lo bf16),
// chunk-XOR swizzled; B tile identical. ldmatrix.x4 fragment loads.
#define STAGE_B 32768
#define TILE_B  16384

__device__ __forceinline__ void cp16(uint32_t dst, const void* src) {
    asm volatile("cp.async.cg.shared.global [%0], [%1], 16;\n" :: "r"(dst), "l"(src));
}
__device__ __forceinline__ void ldsm4(uint32_t* r, uint32_t addr) {
    asm volatile("ldmatrix.sync.aligned.m8n8.x4.shared.b16 {%0,%1,%2,%3}, [%4];"
                 : "=r"(r[0]), "=r"(r[1]), "=r"(r[2]), "=r"(r[3]) : "r"(addr));
}

#define MMA_BF16(d, a, b0, b1)                                                \
    asm volatile(                                                             \
        "mma.sync.aligned.m16n8k16.row.col.f32.bf16.bf16.f32 "                \
        "{%0,%1,%2,%3},{%4,%5,%6,%7},{%8,%9},{%0,%1,%2,%3};"                  \
        : "+f"(d[0]), "+f"(d[1]), "+f"(d[2]), "+f"(d[3])                      \
        : "r"(a[0]), "r"(a[1]), "r"(a[2]), "r"(a[3]), "r"(b0), "r"(b1))

__device__ __forceinline__ void stage_load(
    uint32_t sb, const __nv_bfloat16* __restrict__ Ah, const __nv_bfloat16* __restrict__ Al,
    const __nv_bfloat16* __restrict__ Bh, const __nv_bfloat16* __restrict__ Bl,
    int row0, int col0, int k0, int tid)
{
#pragma unroll
    for (int i = 0; i < 8; i++) {
        int cid = tid + i * 256;          // 0..2047
        int w   = cid & 1023;
        int row = w >> 3;
        int ch  = w & 7;
        int kel = (ch & 3) * 8;
        uint32_t dst = sb + (cid >> 10) * TILE_B + row * 128 + (((ch ^ (row & 7))) << 4);
        if (cid < 1024) {
            const __nv_bfloat16* src = (ch < 4) ? Ah : Al;
            cp16(dst, src + (size_t)(row0 + row) * KDIM + k0 + kel);
        } else {
            const __nv_bfloat16* src = (ch < 4) ? Bh : Bl;
            cp16(dst, src + (size_t)(col0 + row) * KDIM + k0 + kel);
        }
    }
}

// WHICH: 0 = qkv, 1 = proj
template <int WHICH>
__global__ __launch_bounds__(256, 1) void gemm_bf16(const float* __restrict__ bias,
                                                    float* __restrict__ Cout)
{
    constexpr int NT = (WHICH == 0) ? D3 : DIM;
    const __nv_bfloat16* Ah = (WHICH == 0) ? g_x_hi : g_att_hi;
    const __nv_bfloat16* Al = (WHICH == 0) ? g_x_lo : g_att_lo;
    const __nv_bfloat16* Bh = (WHICH == 0) ? g_wq_hi : g_wp_hi;
    const __nv_bfloat16* Bl = (WHICH == 0) ? g_wq_lo : g_wp_lo;
    float* C = (WHICH == 0) ? g_qkv : Cout;

    extern __shared__ char sm[];
    const int tid  = threadIdx.x;
    const int row0 = blockIdx.x * 128;
    const int col0 = blockIdx.y * 128;
    const int lane = tid & 31, warp = tid >> 5;
    const int wm = warp & 1, wn = warp >> 1;      // 2 x 4 warp grid; warp tile 64x32
    const int g = lane >> 2, t = lane & 3;
    const int lr = lane & 15, ls = lane >> 4;

    uint32_t sbase = (uint32_t)__cvta_generic_to_shared(sm);

    float acc[4][4][4] = {};

    stage_load(sbase, Ah, Al, Bh, Bl, row0, col0, 0, tid);
    asm volatile("cp.async.commit_group;\n" ::: "memory");

    for (int kt = 0; kt < 12; kt++) {
        if (kt < 11) {
            stage_load(sbase + ((kt + 1) & 1) * STAGE_B, Ah, Al, Bh, Bl,
                       row0, col0, (kt + 1) * 32, tid);
            asm volatile("cp.async.commit_group;\n" ::: "memory");
            asm volatile("cp.async.wait_group 1;\n" ::: "memory");
        } else {
            asm volatile("cp.async.wait_group 0;\n" ::: "memory");
        }
        __syncthreads();

        uint32_t sA = sbase + (kt & 1) * STAGE_B;
        uint32_t sB = sA + TILE_B;

#pragma unroll
        for (int kg = 0; kg < 2; kg++) {
            uint32_t ah[4][4], al[4][4], bh[2][4], bl[2][4];
#pragma unroll
            for (int mt = 0; mt < 4; mt++) {
                int row = wm * 64 + mt * 16 + lr;
                uint32_t rb = sA + row * 128;
                int swz = row & 7;
                ldsm4(ah[mt], rb + (((kg * 2 + ls) ^ swz) << 4));
                ldsm4(al[mt], rb + (((4 + kg * 2 + ls) ^ swz) << 4));
            }
#pragma unroll
            for (int p = 0; p < 2; p++) {
                int row = wn * 32 + p * 16 + lr;
                uint32_t rb = sB + row * 128;
                int swz = row & 7;
                ldsm4(bh[p], rb + (((kg * 2 + ls) ^ swz) << 4));
                ldsm4(bl[p], rb + (((4 + kg * 2 + ls) ^ swz) << 4));
            }
            // hi*hi, hi*lo, lo*hi — 16 independent MMAs per pass
#pragma unroll
            for (int mt = 0; mt < 4; mt++)
#pragma unroll
                for (int nt = 0; nt < 4; nt++)
                    MMA_BF16(acc[mt][nt], ah[mt], bh[nt >> 1][nt & 1], bh[nt >> 1][(nt & 1) + 2]);
#pragma unroll
            for (int mt = 0; mt < 4; mt++)
#pragma unroll
                for (int nt = 0; nt < 4; nt++)
                    MMA_BF16(acc[mt][nt], ah[mt], bl[nt >> 1][nt & 1], bl[nt >> 1][(nt & 1) + 2]);
#pragma unroll
            for (int mt = 0; mt < 4; mt++)
#pragma unroll
                for (int nt = 0; nt < 4; nt++)
                    MMA_BF16(acc[mt][nt], al[mt], bh[nt >> 1][nt & 1], bh[nt >> 1][(nt & 1) + 2]);
        }
        __syncthreads();
    }

#pragma unroll
    for (int nt = 0; nt < 4; nt++) {
        int ce = col0 + wn * 32 + nt * 8 + t * 2;
        float b0 = bias[ce], b1 = bias[ce + 1];
#pragma unroll
        for (int mt = 0; mt < 4; mt++) {
            int re = row0 + wm * 64 + mt * 16 + g;
            float* p0 = C + (size_t)re * NT + ce;
            p0[0] = acc[mt][nt][0] + b0;
            p0[1] = acc[mt][nt][1] + b1;
            float* p1 = p0 + (size_t)8 * NT;
            p1[0] = acc[mt][nt][2] + b0;
            p1[1] = acc[mt][nt][3] + b1;
        }
    }
}

// ---------------- attention: register-tiled, quad-parallel softmax ----------
#define QS 52   // padded row stride (floats): conflict-free strided reads
__global__ __launch_bounds__(160) void attn_kernel() {
    const int m    = blockIdx.x;
    const int head = blockIdx.y;
    __shared__ float qs[VTOK][QS];
    __shared__ float ks[VTOK][QS];
    __shared__ float vs[VTOK][QS];
    __shared__ float ps[VTOK][VTOK];
    __shared__ int   rid[VTOK];
    __shared__ int   pix[VTOK];

    const int t = threadIdx.x;
    if (t < VTOK) {
        int wi = m & 63;
        int i  = (wi >> 3) * WSZ + t / WSZ;
        int j  = (wi & 7)  * WSZ + t % WSZ;
        rid[t] = ((i < 45) ? 2 : 0) + ((j < 45) ? 1 : 0);
        int b = m >> 6;
        int h = (i < 45) ? i + 3 : i - 45;
        int w = (j < 45) ? j + 3 : j - 45;
        pix[t] = (b * HW + h) * HW + w;
    }
    __syncthreads();

    for (int idx = t; idx < 3 * VTOK * 12; idx += 160) {
        int t3  = idx / (VTOK * 12);
        int rem = idx - t3 * (VTOK * 12);
        int r = rem / 12;
        int c = rem - r * 12;
        float4 f = *(const float4*)(g_qkv + (size_t)pix[r] * D3 + t3 * DIM + head * HDI + c * 4);
        float* dst = (t3 == 0) ? &qs[r][c * 4] : (t3 == 1) ? &ks[r][c * 4] : &vs[r][c * 4];
        *(float4*)dst = f;
    }
    __syncthreads();

    if (t < 144) {
        const int v = t >> 2, sub = t & 3, u0 = sub * 9;
        const unsigned mask = (t >= 128) ? 0x0000FFFFu : 0xFFFFFFFFu;
        float4 qv[12];
#pragma unroll
        for (int c = 0; c < 12; c++) qv[c] = *(float4*)&qs[v][c * 4];
        const int rv = rid[v];
        float s[9];
#pragma unroll
        for (int j = 0; j < 9; j++) {
            int u = u0 + j;
            float acc = 0.f;
#pragma unroll
            for (int c = 0; c < 12; c++) {
                float4 kv = *(float4*)&ks[u][c * 4];
                acc += qv[c].x * kv.x + qv[c].y * kv.y + qv[c].z * kv.z + qv[c].w * kv.w;
            }
            s[j] = (rv == rid[u]) ? acc * SCALE : -1e30f;
        }
        float mx = s[0];
#pragma unroll
        for (int j = 1; j < 9; j++) mx = fmaxf(mx, s[j]);
        mx = fmaxf(mx, __shfl_xor_sync(mask, mx, 1));
        mx = fmaxf(mx, __shfl_xor_sync(mask, mx, 2));
        float sum = 0.f;
#pragma unroll
        for (int j = 0; j < 9; j++) { s[j] = __expf(s[j] - mx); sum += s[j]; }
        sum += __shfl_xor_sync(mask, sum, 1);
        sum += __shfl_xor_sync(mask, sum, 2);
        float inv = 1.f / sum;
#pragma unroll
        for (int j = 0; j < 9; j++) ps[v][u0 + j] = s[j] * inv;
    }
    __syncthreads();

    if (t < 144) {
        const int v = t >> 2, dc = t & 3;   // 12-float strip
        float4 a0 = {0,0,0,0}, a1 = {0,0,0,0}, a2 = {0,0,0,0};
#pragma unroll 4
        for (int u = 0; u < VTOK; u++) {
            float p = ps[v][u];
            const float* vp = &vs[u][dc * 12];
            float4 v0 = *(const float4*)(vp);
            float4 v1 = *(const float4*)(vp + 4);
            float4 v2 = *(const float4*)(vp + 8);
            a0.x += p * v0.x; a0.y += p * v0.y; a0.z += p * v0.z; a0.w += p * v0.w;
            a1.x += p * v1.x; a1.y += p * v1.y; a1.z += p * v1.z; a1.w += p * v1.w;
            a2.x += p * v2.x; a2.y += p * v2.y; a2.z += p * v2.z; a2.w += p * v2.w;
        }
        float o[12] = {a0.x,a0.y,a0.z,a0.w,a1.x,a1.y,a1.z,a1.w,a2.x,a2.y,a2.z,a2.w};
        uint32_t H[6], L[6];
#pragma unroll
        for (int c = 0; c < 6; c++) {
            uint16_t h0, h1, l0, l1;
            split2(o[c * 2 + 0], h0, l0);
            split2(o[c * 2 + 1], h1, l1);
            H[c] = (uint32_t)h0 | ((uint32_t)h1 << 16);
            L[c] = (uint32_t)l0 | ((uint32_t)l1 << 16);
        }
        size_t off = (size_t)pix[v] * DIM + head * HDI + dc * 12;
        uint2* ph = (uint2*)(g_att_hi + off);
        uint2* pl = (uint2*)(g_att_lo + off);
        ph[0] = make_uint2(H[0], H[1]); ph[1] = make_uint2(H[2], H[3]); ph[2] = make_uint2(H[4], H[5]);
        pl[0] = make_uint2(L[0], L[1]); pl[1] = make_uint2(L[2], L[3]); pl[2] = make_uint2(L[4], L[5]);
    }
}

extern "C" void kernel_launch(void* const* d_in, const int* in_sizes, int n_in,
                              void* d_out, int out_size) {
    const float* x      = (const float*)d_in[0];
    const float* w_qkv  = (const float*)d_in[1];
    const float* b_qkv  = (const float*)d_in[2];
    const float* w_proj = (const float*)d_in[3];
    const float* b_proj = (const float*)d_in[4];
    float* out = (float*)d_out;

    cudaFuncSetAttribute(gemm_bf16<0>, cudaFuncAttributeMaxDynamicSharedMemorySize, 2 * STAGE_B);
    cudaFuncSetAttribute(gemm_bf16<1>, cudaFuncAttributeMaxDynamicSharedMemorySize, 2 * STAGE_B);

    split_x<<<27648, 256>>>(x);
    split_w<D3><<<(KDIM * D3) / 256, 256>>>(w_qkv);
    split_w<DIM><<<(KDIM * DIM) / 256, 256>>>(w_proj);

    gemm_bf16<0><<<dim3(TOK / 128, D3 / 128), 256, 2 * STAGE_B>>>(b_qkv, nullptr);
    attn_kernel<<<dim3(NM, NHE), 160>>>();
    gemm_bf16<1><<<dim3(TOK / 128, DIM / 128), 256, 2 * STAGE_B>>>(b_proj, out);
}